// round 15
// baseline (speedup 1.0000x reference)
#include <cuda_runtime.h>
#include <cuda_bf16.h>

#define VOCAB    128000
#define HISTLEN  2048
#define TOPK     15
#define NBLK     125           // 125 * 1024 == 128000 exactly (scalar)
#define NTHR     1024
#define NWARP    (NTHR / 32)   // 32
#define NWORDS   (VOCAB / 32)  // 4000 bitmap words
#define NEG_KEY  0ull

// -------- device scratch (allocations forbidden; self-cleaning) --------
__device__ unsigned long long g_btop[NBLK * TOPK];   // fully rewritten each call
__device__ float              g_lmax, g_pivot, g_S;
__device__ unsigned long long g_amax;                // reset after use
__device__ unsigned           g_cnt2, g_cnt3;        // reset by releaser
__device__ volatile unsigned  g_gen2;                // monotonic generation

// monotone map float -> unsigned (total order; NaN above +inf) + inverse
__device__ __forceinline__ unsigned ordered(float f) {
    unsigned u = __float_as_uint(f);
    return u ^ ((u & 0x80000000u) ? 0xFFFFFFFFu : 0x80000000u);
}
__device__ __forceinline__ float unordered(unsigned x) {
    unsigned u = (x & 0x80000000u) ? (x ^ 0x80000000u) : (x ^ 0xFFFFFFFFu);
    return __uint_as_float(u);
}
__device__ __forceinline__ unsigned long long make_key(float v, int i) {
    return ((unsigned long long)ordered(v) << 32)
         | (unsigned long long)(0xFFFFFFFFu - (unsigned)i);
}
__device__ __forceinline__ unsigned long long warp_max(unsigned long long k) {
    #pragma unroll
    for (int off = 16; off; off >>= 1) {
        unsigned long long o = __shfl_xor_sync(0xffffffffu, k, off);
        if (o > k) k = o;
    }
    return k;
}
// extract current max of shared slice [lo,hi) (warp-collective), pop it
__device__ __forceinline__ unsigned long long
slice_extract(volatile unsigned long long* arr, int lo, int hi, int lane) {
    unsigned long long lm = NEG_KEY; int lp = lo;
    for (int j = lo + lane; j < hi; j += 32) {
        unsigned long long x = arr[j];
        if (x > lm) { lm = x; lp = j; }
    }
    unsigned long long m = warp_max(lm);
    if (lm == m && lm != NEG_KEY) arr[lp] = NEG_KEY;  // unique keys: one owner
    __syncwarp();
    return m;
}

__global__ void __launch_bounds__(NTHR, 1)
k_fused(const float* __restrict__ logits, const int* __restrict__ y,
        const float* __restrict__ noise, float* __restrict__ out, int out_size) {
    __shared__ unsigned           sbm[NWORDS];           // 16 KB bitmap
    __shared__ unsigned long long sall[NBLK * TOPK];     // 15 KB (merge block)
    __shared__ unsigned long long swtop[NWARP * TOPK];   // 480 keys
    __shared__ unsigned long long s2[8 * TOPK];          // 120 keys
    __shared__ unsigned long long red[NWARP];
    __shared__ float s_piv, s_lmax, s_S;
    __shared__ int   s_flag;

    const int tid = threadIdx.x, lane = tid & 31, w = tid >> 5;
    const int i = blockIdx.x * NTHR + tid;               // exactly covers VOCAB

    // ---- early independent loads (hide DRAM latency behind bitmap build) ---
    float lv = logits[i];
    float nv = noise[i];

    // ---- block-local membership bitmap (redundant per block; barrier-free) -
    for (int j = tid; j < NWORDS; j += NTHR) sbm[j] = 0u;
    __syncthreads();
    {
        int t0 = tid, t1 = tid + NTHR;                   // HISTLEN == 2 * NTHR
        int p0 = y[t0], p1 = y[t1];
        if (blockIdx.x == 0 && out_size >= HISTLEN + 2) {
            out[1 + t0] = (float)p0;                     // y_new copy, exact <2^24
            out[1 + t1] = (float)p1;
        }
        p0 = min(max(p0, 0), VOCAB - 1);                 // clamp: OOB impossible
        p1 = min(max(p1, 0), VOCAB - 1);
        atomicOr(&sbm[p0 >> 5], 1u << (p0 & 31));
        atomicOr(&sbm[p1 >> 5], 1u << (p1 & 31));
    }
    __syncthreads();

    // ---- penalty (regs). _rn ops bit-match the f32 reference; value depends
    // only on the ORIGINAL logit so duplicate history tokens are harmless.
    if ((sbm[i >> 5] >> (i & 31)) & 1u)
        lv = (lv < 0.0f) ? __fmul_rn(lv, 1.35f) : __fdiv_rn(lv, 1.35f);

    // ---- warp bitonic sort (ascending) of 32 unique keys; 15 stages ---------
    unsigned long long key = make_key(lv, i);
    #pragma unroll
    for (int k = 2; k <= 32; k <<= 1) {
        #pragma unroll
        for (int j = k >> 1; j > 0; j >>= 1) {
            unsigned long long o = __shfl_xor_sync(0xffffffffu, key, j);
            bool up = ((lane & k) == 0);
            bool hi = ((lane & j) != 0);
            unsigned long long mn = (key < o) ? key : o;
            unsigned long long mx = (key < o) ? o : key;
            key = (hi == up) ? mx : mn;
        }
    }
    if (lane >= 32 - TOPK) swtop[w * TOPK + (31 - lane)] = key;  // warp top-15
    __syncthreads();

    // ---- block merge: 480 -> 120 (8 warps x 60) -> 15 (warp 0) --------------
    if (w < 8) {
        int lo = w * 60, hi2 = lo + 60;
        for (int k = 0; k < TOPK; k++) {
            unsigned long long m = slice_extract(swtop, lo, hi2, lane);
            if (lane == 0) s2[w * TOPK + k] = m;
        }
    }
    __syncthreads();
    if (w == 0) {
        for (int k = 0; k < TOPK; k++) {
            unsigned long long m = slice_extract(s2, 0, 8 * TOPK, lane);
            if (lane == 0) g_btop[blockIdx.x * TOPK + k] = m;
        }
    }
    __syncthreads();

    // ---- single grid barrier with FOLDED global merge (1875 keys) -----------
    if (tid == 0) {
        __threadfence();                                 // publish g_btop
        unsigned gen = g_gen2;
        s_flag = (atomicAdd(&g_cnt2, 1u) == NBLK - 1);
        if (!s_flag) { while (g_gen2 == gen) __nanosleep(32); }
    }
    __syncthreads();
    if (s_flag) {                                        // last arriver merges
        __threadfence();                                 // acquire all g_btop
        for (int j = tid; j < NBLK * TOPK; j += NTHR) sall[j] = g_btop[j];
        __syncthreads();
        {   // level 1: 32 warps x 59 keys -> 480 (reuse swtop)
            int lo = w * 59, hi2 = min(lo + 59, NBLK * TOPK);
            for (int k = 0; k < TOPK; k++) {
                unsigned long long m = slice_extract(sall, lo, hi2, lane);
                if (lane == 0) swtop[w * TOPK + k] = m;
            }
        }
        __syncthreads();
        if (w < 8) {    // level 2: 8 warps x 60 -> 120
            int lo = w * 60, hi2 = lo + 60;
            for (int k = 0; k < TOPK; k++) {
                unsigned long long m = slice_extract(swtop, lo, hi2, lane);
                if (lane == 0) s2[w * TOPK + k] = m;
            }
        }
        __syncthreads();
        if (w == 0) {   // level 3: 120 -> 15, then lmax/pivot/S
            float top[TOPK];
            for (int k = 0; k < TOPK; k++) {
                unsigned long long m = slice_extract(s2, 0, 8 * TOPK, lane);
                top[k] = unordered((unsigned)(m >> 32));
            }
            if (lane == 0) {
                float lmax = top[0];
                float S = 0.0f;                          // kept set IS these 15
                for (int k = 0; k < TOPK; k++) S += expf(top[k] - lmax);
                g_lmax = lmax; g_pivot = top[TOPK - 1]; g_S = S;
            }
        }
        __syncthreads();
        if (tid == 0) {                                  // release spinners
            g_cnt2 = 0u; __threadfence(); g_gen2 = g_gen2 + 1u;
        }
    }
    __syncthreads();
    if (tid == 0) {                                      // acquire pivot
        __threadfence();
        s_piv = g_pivot; s_lmax = g_lmax; s_S = g_S;
    }
    __syncthreads();

    // ---- argmax(probs/noise) from REGISTERS (no reload of inputs) -----------
    // kept: (exp(l-lmax)/S)/noise ; masked: 0/noise (exact +-0 / NaN like ref).
    // +-0 unify to ONE key (first-index ties, IEEE +0==-0 under jnp.argmax);
    // NaN keys order above everything (NaN propagation).
    {
        const float piv = s_piv, lmax = s_lmax, S = s_S;
        float v = (lv >= piv) ? __fdiv_rn(__fdiv_rn(expf(lv - lmax), S), nv)
                              : __fdiv_rn(0.0f, nv);
        unsigned ov = (v == 0.0f) ? 0x80000000u : ordered(v);
        unsigned long long b = ((unsigned long long)ov << 32)
                             | (unsigned long long)(0xFFFFFFFFu - (unsigned)i);
        b = warp_max(b);
        if (lane == 0) red[w] = b;
    }
    __syncthreads();
    if (w == 0) {
        unsigned long long m = red[lane];                // NWARP == 32
        m = warp_max(m);
        if (lane == 0) atomicMax(&g_amax, m);
    }
    __syncthreads();

    // ---- exit counter: last block writes the sample --------------------------
    if (tid == 0) {
        __threadfence();
        if (atomicAdd(&g_cnt3, 1u) == NBLK - 1) {
            g_cnt3 = 0u;                                 // self-clean
            unsigned long long m = atomicAdd(&g_amax, 0ull);
            g_amax = 0ull;                               // self-clean
            float fidx = (float)(int)(0xFFFFFFFFu - (unsigned)(m & 0xFFFFFFFFull));
            out[0] = fidx;                                        // samples
            if (out_size >= HISTLEN + 2) out[1 + HISTLEN] = fidx; // y_new tail
            for (int j = HISTLEN + 2; j < out_size; j++) out[j] = fidx;
        }
    }
}

extern "C" void kernel_launch(void* const* d_in, const int* in_sizes, int n_in,
                              void* d_out, int out_size) {
    // y = the size-2048 tensor; among the remaining two (metadata order),
    // logits precedes noise (validated rounds 9-14).
    int iy = 1;
    for (int i = 0; i < n_in; i++) if (in_sizes[i] == HISTLEN) { iy = i; break; }
    int fl[2]; int nf = 0;
    for (int i = 0; i < n_in && nf < 2; i++) if (i != iy) fl[nf++] = i;

    const float* logits = (const float*)d_in[fl[0]];
    const float* noise  = (const float*)d_in[fl[1]];
    const int*   y      = (const int*)d_in[iy];

    k_fused<<<NBLK, NTHR>>>(logits, y, noise, (float*)d_out, out_size);
}

// round 16
// speedup vs baseline: 1.0477x; 1.0477x over previous
#include <cuda_runtime.h>
#include <cuda_bf16.h>

#define VOCAB    128000
#define HISTLEN  2048
#define TOPK     15
#define NBLK     125           // 125 * 1024 == 128000 exactly
#define NTHR     1024
#define NWARP    (NTHR / 32)   // 32
#define NEG_KEY  0ull

// -------- device scratch (allocations forbidden; self-cleaning) --------
__device__ unsigned long long g_btop[NBLK * TOPK];   // fully rewritten each call
__device__ float              g_lmax, g_pivot, g_S;
__device__ unsigned long long g_amax;                // reset after use
__device__ unsigned           g_cnt1, g_cnt2;        // reset by last block

// monotone map float -> unsigned (total order; NaN above +inf) + inverse
__device__ __forceinline__ unsigned ordered(float f) {
    unsigned u = __float_as_uint(f);
    return u ^ ((u & 0x80000000u) ? 0xFFFFFFFFu : 0x80000000u);
}
__device__ __forceinline__ float unordered(unsigned x) {
    unsigned u = (x & 0x80000000u) ? (x ^ 0x80000000u) : (x ^ 0xFFFFFFFFu);
    return __uint_as_float(u);
}
__device__ __forceinline__ unsigned long long make_key(float v, int i) {
    return ((unsigned long long)ordered(v) << 32)
         | (unsigned long long)(0xFFFFFFFFu - (unsigned)i);
}
__device__ __forceinline__ unsigned long long warp_max(unsigned long long k) {
    #pragma unroll
    for (int off = 16; off; off >>= 1) {
        unsigned long long o = __shfl_xor_sync(0xffffffffu, k, off);
        if (o > k) k = o;
    }
    return k;
}
// extract current max of shared slice [lo,hi) (warp-collective), pop it
__device__ __forceinline__ unsigned long long
slice_extract(volatile unsigned long long* arr, int lo, int hi, int lane) {
    unsigned long long lm = NEG_KEY; int lp = lo;
    for (int j = lo + lane; j < hi; j += 32) {
        unsigned long long x = arr[j];
        if (x > lm) { lm = x; lp = j; }
    }
    unsigned long long m = warp_max(lm);
    if (lm == m && lm != NEG_KEY) arr[lp] = NEG_KEY;  // unique keys: one owner
    __syncwarp();
    return m;
}

// Build THIS BLOCK's 32-word membership bitmap (covers its 1024 tokens only).
// Every block scans y (2 loads/thread); tokens outside the range are ignored.
// Returns the penalized logit for index i (thread's own element).
__device__ __forceinline__ float
range_penalty(float lv, int i, const int* __restrict__ y, unsigned* sbm,
              int tid, bool write_copy, float* __restrict__ out, int out_size) {
    if (tid < 32) sbm[tid] = 0u;
    __syncthreads();
    int t0 = tid, t1 = tid + NTHR;                    // HISTLEN == 2 * NTHR
    int p0 = y[t0], p1 = y[t1];
    if (write_copy && out_size >= HISTLEN + 2) {
        out[1 + t0] = (float)p0;                      // y_new copy, exact <2^24
        out[1 + t1] = (float)p1;
    }
    p0 = min(max(p0, 0), VOCAB - 1);                  // clamp: OOB impossible
    p1 = min(max(p1, 0), VOCAB - 1);
    if ((p0 >> 10) == (int)blockIdx.x)
        atomicOr(&sbm[(p0 & 1023) >> 5], 1u << (p0 & 31));
    if ((p1 >> 10) == (int)blockIdx.x)
        atomicOr(&sbm[(p1 & 1023) >> 5], 1u << (p1 & 31));
    __syncthreads();
    // _rn ops bit-match the f32 reference; value depends only on the ORIGINAL
    // logit so duplicate history tokens are harmless.
    if ((sbm[(i & 1023) >> 5] >> (i & 31)) & 1u)
        lv = (lv < 0.0f) ? __fmul_rn(lv, 1.35f) : __fdiv_rn(lv, 1.35f);
    return lv;
}

// K1 (125 x 1024): per-block exact top-15 -> g_btop; LAST block (others have
// exited) merges 1875 keys -> lmax / pivot / softmax denominator S.
__global__ void __launch_bounds__(NTHR, 1)
k1_top(const float* __restrict__ logits, const int* __restrict__ y,
       float* __restrict__ out, int out_size) {
    __shared__ unsigned           sbm[32];
    __shared__ unsigned long long sall[NBLK * TOPK];    // 15 KB (last block)
    __shared__ unsigned long long swtop[NWARP * TOPK];  // 480
    __shared__ unsigned long long s2[8 * TOPK];         // 120
    __shared__ int s_flag;

    const int tid = threadIdx.x, lane = tid & 31, w = tid >> 5;
    const int i = blockIdx.x * NTHR + tid;              // exactly covers VOCAB

    float lv = logits[i];                               // early load
    lv = range_penalty(lv, i, y, sbm, tid, blockIdx.x == 0, out, out_size);

    // warp bitonic sort (ascending) of 32 unique keys: 15 shuffle stages
    unsigned long long key = make_key(lv, i);
    #pragma unroll
    for (int k = 2; k <= 32; k <<= 1) {
        #pragma unroll
        for (int j = k >> 1; j > 0; j >>= 1) {
            unsigned long long o = __shfl_xor_sync(0xffffffffu, key, j);
            bool up = ((lane & k) == 0);
            bool hi = ((lane & j) != 0);
            unsigned long long mn = (key < o) ? key : o;
            unsigned long long mx = (key < o) ? o : key;
            key = (hi == up) ? mx : mn;
        }
    }
    if (lane >= 32 - TOPK) swtop[w * TOPK + (31 - lane)] = key;  // warp top-15
    __syncthreads();
    // block merge: 480 -> 120 (8 warps x 60) -> 15 (warp 0)
    if (w < 8) {
        int lo = w * 60, hi2 = lo + 60;
        for (int k = 0; k < TOPK; k++) {
            unsigned long long m = slice_extract(swtop, lo, hi2, lane);
            if (lane == 0) s2[w * TOPK + k] = m;
        }
    }
    __syncthreads();
    if (w == 0) {
        for (int k = 0; k < TOPK; k++) {
            unsigned long long m = slice_extract(s2, 0, 8 * TOPK, lane);
            if (lane == 0) g_btop[blockIdx.x * TOPK + k] = m;
        }
    }
    __syncthreads();

    // exit counter: LAST block merges (no spinning anywhere)
    if (tid == 0) {
        __threadfence();                                // publish g_btop
        s_flag = (atomicAdd(&g_cnt1, 1u) == NBLK - 1);
        if (s_flag) g_cnt1 = 0u;                        // self-clean
    }
    __syncthreads();
    if (!s_flag) return;
    __threadfence();                                    // acquire all g_btop
    for (int j = tid; j < NBLK * TOPK; j += NTHR) sall[j] = g_btop[j];
    __syncthreads();
    {   // level 1: 32 warps x 59 keys -> 480
        int lo = w * 59, hi2 = min(lo + 59, NBLK * TOPK);
        for (int k = 0; k < TOPK; k++) {
            unsigned long long m = slice_extract(sall, lo, hi2, lane);
            if (lane == 0) swtop[w * TOPK + k] = m;
        }
    }
    __syncthreads();
    if (w < 8) {        // level 2: 8 warps x 60 -> 120
        int lo = w * 60, hi2 = lo + 60;
        for (int k = 0; k < TOPK; k++) {
            unsigned long long m = slice_extract(swtop, lo, hi2, lane);
            if (lane == 0) s2[w * TOPK + k] = m;
        }
    }
    __syncthreads();
    if (w == 0) {       // level 3: 120 -> 15; then lmax / pivot / S
        float top[TOPK];
        for (int k = 0; k < TOPK; k++) {
            unsigned long long m = slice_extract(s2, 0, 8 * TOPK, lane);
            top[k] = unordered((unsigned)(m >> 32));
        }
        if (lane == 0) {
            float lmax = top[0];
            float S = 0.0f;                             // kept set IS these 15
            for (int k = 0; k < TOPK; k++) S += expf(top[k] - lmax);
            g_lmax = lmax; g_pivot = top[TOPK - 1]; g_S = S;
        }
    }
}

// K2 (125 x 1024): argmax(probs/noise); LAST block writes the sample.
// kept: (exp(l-lmax)/S)/noise ; masked: 0/noise (exact +-0 / NaN like ref).
// +-0 unify to ONE key (first-index ties, IEEE +0==-0 under jnp.argmax);
// NaN keys order above everything (NaN propagation).
__global__ void __launch_bounds__(NTHR, 1)
k2_argmax(const float* __restrict__ logits, const int* __restrict__ y,
          const float* __restrict__ noise, float* __restrict__ out, int out_size) {
    __shared__ unsigned           sbm[32];
    __shared__ unsigned long long red[NWARP];
    __shared__ int s_flag;
    const int tid = threadIdx.x, lane = tid & 31, w = tid >> 5;
    const int i = blockIdx.x * NTHR + tid;

    float lv = logits[i];                               // early loads
    float nv = noise[i];
    lv = range_penalty(lv, i, y, sbm, tid, false, out, out_size);

    const float piv = g_pivot, lmax = g_lmax, S = g_S;  // written in K1
    float v = (lv >= piv) ? __fdiv_rn(__fdiv_rn(expf(lv - lmax), S), nv)
                          : __fdiv_rn(0.0f, nv);
    unsigned ov = (v == 0.0f) ? 0x80000000u : ordered(v);
    unsigned long long b = ((unsigned long long)ov << 32)
                         | (unsigned long long)(0xFFFFFFFFu - (unsigned)i);
    b = warp_max(b);
    if (lane == 0) red[w] = b;
    __syncthreads();
    if (w == 0) {
        unsigned long long m = red[lane];               // NWARP == 32
        m = warp_max(m);
        if (lane == 0) atomicMax(&g_amax, m);
    }
    __syncthreads();
    if (tid == 0) {
        __threadfence();
        s_flag = (atomicAdd(&g_cnt2, 1u) == NBLK - 1);
        if (s_flag) g_cnt2 = 0u;                        // self-clean
    }
    __syncthreads();
    if (!s_flag) return;
    if (tid == 0) {
        unsigned long long m = atomicAdd(&g_amax, 0ull);   // coherent read
        g_amax = 0ull;                                  // self-clean
        float fidx = (float)(int)(0xFFFFFFFFu - (unsigned)(m & 0xFFFFFFFFull));
        out[0] = fidx;                                            // samples
        if (out_size >= HISTLEN + 2) out[1 + HISTLEN] = fidx;     // y_new tail
        for (int j = HISTLEN + 2; j < out_size; j++) out[j] = fidx;
    }
}

extern "C" void kernel_launch(void* const* d_in, const int* in_sizes, int n_in,
                              void* d_out, int out_size) {
    // y = the size-2048 tensor; among the remaining two (metadata order),
    // logits precedes noise (validated rounds 9-15).
    int iy = 1;
    for (int i = 0; i < n_in; i++) if (in_sizes[i] == HISTLEN) { iy = i; break; }
    int fl[2]; int nf = 0;
    for (int i = 0; i < n_in && nf < 2; i++) if (i != iy) fl[nf++] = i;

    const float* logits = (const float*)d_in[fl[0]];
    const float* noise  = (const float*)d_in[fl[1]];
    const int*   y      = (const int*)d_in[iy];
    float* out = (float*)d_out;

    k1_top   <<<NBLK, NTHR>>>(logits, y, out, out_size);
    k2_argmax<<<NBLK, NTHR>>>(logits, y, noise, out, out_size);
}